// round 11
// baseline (speedup 1.0000x reference)
#include <cuda_runtime.h>
#include <cuda_fp16.h>
#include <math.h>
#include <stdint.h>

#define CCH   512
#define NPIX  4096
#define BATCH 8
#define SPLITK 4

// ---------------- scratch ----------------
__device__ __half g_Xh[(size_t)BATCH * CCH * NPIX];
__device__ __half g_Xl[(size_t)BATCH * CCH * NPIX];
__device__ __half g_XTh[(size_t)BATCH * CCH * NPIX];
__device__ __half g_XTl[(size_t)BATCH * CCH * NPIX];
__device__ __half g_Wh[4 * CCH * CCH];
__device__ __half g_Wl[4 * CCH * CCH];
__device__ float  g_s [BATCH * CCH];
__device__ float  g_qs[BATCH * CCH];
__device__ float  g_ks[BATCH * CCH];
__device__ float  g_by[BATCH * CCH];
__device__ float  g_bo2[BATCH * CCH];
__device__ float  g_Gp[SPLITK][(size_t)BATCH * CCH * CCH];  // split-K partials
__device__ __half g_Gh[(size_t)BATCH * CCH * CCH];
__device__ __half g_Gl[(size_t)BATCH * CCH * CCH];
__device__ float  g_U [(size_t)BATCH * CCH * CCH];
__device__ float  g_A [BATCH * 64 * 64];                // gamma-folded softmax
__device__ __half g_Wyh[(size_t)BATCH * CCH * CCH];
__device__ __half g_Mh[(size_t)BATCH * CCH * CCH];

__constant__ int c_pm[10] = {0,0,0,0,1,1,1,2,2,3};
__constant__ int c_pn[10] = {0,1,2,3,1,2,3,2,3,3};

// ---------------- helpers ----------------
__device__ __forceinline__ uint32_t smem_u32(const void* p) {
    uint32_t a;
    asm("{ .reg .u64 t; cvta.to.shared.u64 t, %1; cvt.u32.u64 %0, t; }" : "=r"(a) : "l"(p));
    return a;
}
__device__ __forceinline__ void cpasync16(uint32_t dst, const void* src) {
    asm volatile("cp.async.cg.shared.global [%0], [%1], 16;" :: "r"(dst), "l"(src));
}
#define CP_COMMIT() asm volatile("cp.async.commit_group;" ::: "memory")
template<int N> __device__ __forceinline__ void cp_wait() {
    asm volatile("cp.async.wait_group %0;" :: "n"(N) : "memory");
}
__device__ __forceinline__ void ldsm4(uint32_t* r, uint32_t addr) {
    asm volatile("ldmatrix.sync.aligned.m8n8.x4.shared.b16 {%0,%1,%2,%3}, [%4];"
                 : "=r"(r[0]), "=r"(r[1]), "=r"(r[2]), "=r"(r[3]) : "r"(addr));
}
__device__ __forceinline__ void ldsm4t(uint32_t* r, uint32_t addr) {
    asm volatile("ldmatrix.sync.aligned.m8n8.x4.trans.shared.b16 {%0,%1,%2,%3}, [%4];"
                 : "=r"(r[0]), "=r"(r[1]), "=r"(r[2]), "=r"(r[3]) : "r"(addr));
}
__device__ __forceinline__ void mma16816(float* c, const uint32_t* a, uint32_t b0, uint32_t b1) {
    asm volatile("mma.sync.aligned.m16n8k16.row.col.f32.f16.f16.f32 "
                 "{%0,%1,%2,%3}, {%4,%5,%6,%7}, {%8,%9}, {%0,%1,%2,%3};"
                 : "+f"(c[0]), "+f"(c[1]), "+f"(c[2]), "+f"(c[3])
                 : "r"(a[0]), "r"(a[1]), "r"(a[2]), "r"(a[3]), "r"(b0), "r"(b1));
}

#define A_ST 40
#define B_ST 136
#define A_MAT (128 * A_ST)
#define B_MAT (32 * B_ST)
#define STG_FULL (2 * A_MAT + 2 * B_MAT)
#define STG_LITE (A_MAT + B_MAT)
#define SMEM_FULL (4 * STG_FULL * 2)
#define SMEM_LITE (4 * STG_LITE * 2)

// ---------------------------------------------------------------------------
// hgemm: out[b][m][n] = sum_k W[m,k] * X[b][k][n] (+bias[b][m]) (+resid)
// FULL: 3-pass double-fp16. TRI: symmetric upper-triangle tile remap.
// HOUT: write __half output.
// Inner loop hoists BOTH k16 steps' ldmatrix fragments before the MMA block
// so ldsm latency overlaps MMA issue (frag regs [2][..] ~116 regs total).
// ---------------------------------------------------------------------------
template<bool RESID, bool FULL, bool TRI, bool HOUT>
__global__ void __launch_bounds__(512, 1) hgemm(
    const __half* __restrict__ Whg, const __half* __restrict__ Wlg,
    const __half* __restrict__ Xhg, const __half* __restrict__ Xlg,
    const float* __restrict__ bias, const float* __restrict__ resid,
    void* __restrict__ out,
    int npix, int kfull, int nch,
    size_t wstride, size_t xstride, int bstride, size_t oslice)
{
    extern __shared__ __half sm[];
    const uint32_t sb = smem_u32(sm);
    constexpr int STG = FULL ? STG_FULL : STG_LITE;
    constexpr int OFF_AH = 0, OFF_AL = A_MAT;
    constexpr int OFF_BH = FULL ? 2 * A_MAT : A_MAT;
    constexpr int OFF_BL = 2 * A_MAT + B_MAT;

    const int tid = threadIdx.x, lane = tid & 31, wid = tid >> 5;
    const int wm = wid >> 2, wn = wid & 3;
    const int b = blockIdx.z & 7, ksl = blockIdx.z >> 3;
    const int m0 = (TRI ? c_pm[blockIdx.x] : (int)blockIdx.y) * 128;
    const int n0 = (TRI ? c_pn[blockIdx.x] : (int)blockIdx.x) * 128;
    const int kg0 = ksl * nch * 32;
    const __half* Wb  = Whg + (size_t)b * wstride;
    const __half* Wlb = FULL ? Wlg + (size_t)b * wstride : nullptr;
    const __half* Bhp = Xhg + (size_t)b * xstride;
    const __half* Blp = FULL ? Xlg + (size_t)b * xstride : nullptr;
    const size_t obase = (size_t)ksl * oslice;

    const int ar = tid >> 2, ak = (tid & 3) * 8;
    const int br = tid >> 4, bn = (tid & 15) * 8;
    const int quad = lane >> 3, r8 = lane & 7;
    const int qlow = (quad & 1) * 8, qhi = (quad >> 1) * 8;

    float c[2][4][4];
    #pragma unroll
    for (int i = 0; i < 2; i++)
        #pragma unroll
        for (int j = 0; j < 4; j++)
            #pragma unroll
            for (int e = 0; e < 4; e++) c[i][j][e] = 0.f;

    auto issue = [&](int s, int ch) {
        const int k0 = kg0 + ch * 32;
        const uint32_t st = sb + 2 * (s * STG);
        cpasync16(st + 2 * (OFF_AH + ar * A_ST + ak), Wb  + (size_t)(m0 + ar) * kfull + k0 + ak);
        cpasync16(st + 2 * (OFF_BH + br * B_ST + bn), Bhp + (size_t)(k0 + br) * npix + n0 + bn);
        if (FULL) {
            cpasync16(st + 2 * (OFF_AL + ar * A_ST + ak), Wlb + (size_t)(m0 + ar) * kfull + k0 + ak);
            cpasync16(st + 2 * (OFF_BL + br * B_ST + bn), Blp + (size_t)(k0 + br) * npix + n0 + bn);
        }
    };

    issue(0, 0); CP_COMMIT();
    issue(1, 1); CP_COMMIT();

    for (int ch = 0; ch < nch; ch++) {
        const int s = ch & 3;
        if (ch + 2 < nch) { issue((ch + 2) & 3, ch + 2); CP_COMMIT(); }
        if (ch + 2 < nch)      cp_wait<2>();
        else if (ch + 1 < nch) cp_wait<1>();
        else                   cp_wait<0>();
        __syncthreads();

        const uint32_t sbase = sb + 2 * (s * STG);

        // ---- load ALL fragments for both k16 steps up front ----
        uint32_t ah[2][2][4], al[2][2][4], bh[2][2][4], bl[2][2][4];
        #pragma unroll
        for (int k16 = 0; k16 < 2; k16++) {
            #pragma unroll
            for (int mi = 0; mi < 2; mi++) {
                const uint32_t off = 2 * ((uint32_t)(wm * 32 + mi * 16 + r8 + qlow) * A_ST + k16 * 16 + qhi);
                ldsm4(ah[k16][mi], sbase + 2 * OFF_AH + off);
                if (FULL) ldsm4(al[k16][mi], sbase + 2 * OFF_AL + off);
            }
            #pragma unroll
            for (int ni = 0; ni < 2; ni++) {
                const uint32_t off = 2 * ((uint32_t)(k16 * 16 + r8 + qlow) * B_ST + wn * 32 + ni * 16 + qhi);
                ldsm4t(bh[k16][ni], sbase + 2 * OFF_BH + off);
                if (FULL) ldsm4t(bl[k16][ni], sbase + 2 * OFF_BL + off);
            }
        }
        // ---- MMA block ----
        #pragma unroll
        for (int k16 = 0; k16 < 2; k16++)
            #pragma unroll
            for (int mi = 0; mi < 2; mi++)
                #pragma unroll
                for (int j = 0; j < 4; j++) {
                    const int ni = j >> 1, ss = (j & 1) * 2;
                    mma16816(c[mi][j], ah[k16][mi], bh[k16][ni][ss], bh[k16][ni][ss + 1]);
                    if (FULL) {
                        mma16816(c[mi][j], ah[k16][mi], bl[k16][ni][ss], bl[k16][ni][ss + 1]);
                        mma16816(c[mi][j], al[k16][mi], bh[k16][ni][ss], bh[k16][ni][ss + 1]);
                    }
                }
        __syncthreads();
    }

    #pragma unroll
    for (int mi = 0; mi < 2; mi++) {
        #pragma unroll
        for (int rr = 0; rr < 2; rr++) {
            const int m = m0 + wm * 32 + mi * 16 + (lane >> 2) + rr * 8;
            const float bi = bias ? __ldg(&bias[b * bstride + m]) : 0.f;
            const size_t rowoff = ((size_t)b * CCH + m) * npix + n0 + wn * 32 + (lane & 3) * 2;
            #pragma unroll
            for (int j = 0; j < 4; j++) {
                float2 v;
                v.x = c[mi][j][rr * 2 + 0] + bi;
                v.y = c[mi][j][rr * 2 + 1] + bi;
                if (RESID) {
                    float2 r = *(const float2*)&resid[rowoff + j * 8];
                    v.x += r.x; v.y += r.y;
                }
                if (HOUT) {
                    __half2 hv = __halves2half2(__float2half_rn(v.x), __float2half_rn(v.y));
                    *(__half2*)((__half*)out + obase + rowoff + j * 8) = hv;
                } else {
                    *(float2*)((float*)out + obase + rowoff + j * 8) = v;
                }
            }
        }
    }
}

// ---------------------------------------------------------------------------
__global__ void zero_s() { g_s[blockIdx.x * 512 + threadIdx.x] = 0.f; }

// prep_x: coalesced split fp32 -> fp16 hi/lo + row-sum atomic
__global__ void __launch_bounds__(256) prep_x(const float* __restrict__ src) {
    __shared__ float red[256];
    const size_t i = ((size_t)blockIdx.x * 256 + threadIdx.x) * 8;
    float4 v0 = *(const float4*)&src[i];
    float4 v1 = *(const float4*)&src[i + 4];
    const float v[8] = {v0.x, v0.y, v0.z, v0.w, v1.x, v1.y, v1.z, v1.w};
    __half h[8], l[8];
    float ps = 0.f;
    #pragma unroll
    for (int e = 0; e < 8; e++) {
        h[e] = __float2half_rn(v[e]);
        l[e] = __float2half_rn(v[e] - __half2float(h[e]));
        ps += v[e];
    }
    *(uint4*)&g_Xh[i] = *(const uint4*)h;
    *(uint4*)&g_Xl[i] = *(const uint4*)l;
    red[threadIdx.x] = ps; __syncthreads();
    for (int o = 128; o; o >>= 1) {
        if (threadIdx.x < o) red[threadIdx.x] += red[threadIdx.x + o];
        __syncthreads();
    }
    if (threadIdx.x == 0) atomicAdd(&g_s[blockIdx.x >> 1], red[0]);
}

// transpose + split, sourcing the (hi,lo) halves (32 MiB read instead of 64).
// v = hi + lo re-splits to the identical (hi, lo) pair, so GEMM inputs match.
__global__ void __launch_bounds__(256) prep_xT(const float* __restrict__ /*unused*/) {
    __shared__ float s[32][33];
    const int n0 = blockIdx.x * 32, c0 = blockIdx.y * 32, b = blockIdx.z;
    const int tx = threadIdx.x, ty = threadIdx.y;
    #pragma unroll
    for (int i = 0; i < 4; i++) {
        const size_t idx = ((size_t)(b * CCH + c0 + ty + 8 * i)) * NPIX + n0 + tx;
        s[ty + 8 * i][tx] = __half2float(g_Xh[idx]) + __half2float(g_Xl[idx]);
    }
    __syncthreads();
    #pragma unroll
    for (int i = 0; i < 4; i++) {
        const float v = s[tx][ty + 8 * i];
        const __half hi = __float2half_rn(v);
        const size_t idx = ((size_t)b * NPIX + n0 + ty + 8 * i) * CCH + c0 + tx;
        g_XTh[idx] = hi;
        g_XTl[idx] = __float2half_rn(v - __half2float(hi));
    }
}

__global__ void __launch_bounds__(256) prep_w(
    const float* __restrict__ Wq, const float* __restrict__ Wk,
    const float* __restrict__ Wv, const float* __restrict__ Wo)
{
    const int m = blockIdx.y;
    const size_t t = (size_t)blockIdx.x * 256 + threadIdx.x;
    const float* W = (m == 0) ? Wq : (m == 1) ? Wk : (m == 2) ? Wv : Wo;
    const float v = W[t];
    const __half h = __float2half_rn(v);
    g_Wh[(size_t)m * CCH * CCH + t] = h;
    g_Wl[(size_t)m * CCH * CCH + t] = __float2half_rn(v - __half2float(h));
}

// sum SPLITK split-K partials, mirror lower triangle, split to fp16
__global__ void __launch_bounds__(256) splitG() {
    __shared__ float s[32][33];
    const int ti = blockIdx.x, tj = blockIdx.y, b = blockIdx.z;
    const int tx = threadIdx.x, ty = threadIdx.y;
    const size_t base = (size_t)b * CCH * CCH;
    const bool swap = (ti >> 2) > (tj >> 2);
    if (!swap) {
        #pragma unroll
        for (int k = 0; k < 4; k++) {
            const int r = ti * 32 + ty + 8 * k, cc = tj * 32 + tx;
            const size_t o = base + (size_t)r * CCH + cc;
            float v = 0.f;
            #pragma unroll
            for (int p = 0; p < SPLITK; p++) v += g_Gp[p][o];
            const __half hi = __float2half_rn(v);
            g_Gh[o] = hi; g_Gl[o] = __float2half_rn(v - __half2float(hi));
        }
    } else {
        #pragma unroll
        for (int k = 0; k < 4; k++) {
            const int r = tj * 32 + ty + 8 * k, cc = ti * 32 + tx;
            const size_t o = base + (size_t)r * CCH + cc;
            float v = 0.f;
            #pragma unroll
            for (int p = 0; p < SPLITK; p++) v += g_Gp[p][o];
            s[ty + 8 * k][tx] = v;
        }
        __syncthreads();
        #pragma unroll
        for (int k = 0; k < 4; k++) {
            const int r = ti * 32 + ty + 8 * k, cc = tj * 32 + tx;
            const float v = s[tx][ty + 8 * k];
            const __half hi = __float2half_rn(v);
            const size_t o = base + (size_t)r * CCH + cc;
            g_Gh[o] = hi; g_Gl[o] = __float2half_rn(v - __half2float(hi));
        }
    }
}

// qs = Wq s ; ks = Wk s  (grid.z selects matrix)
__global__ void __launch_bounds__(256) gemv_qk(
    const float* __restrict__ Wq, const float* __restrict__ Wk)
{
    const int b = blockIdx.y, m = blockIdx.x * 8 + (threadIdx.x >> 5), lane = threadIdx.x & 31;
    const float* W = blockIdx.z ? Wk : Wq;
    float* o = blockIdx.z ? g_ks : g_qs;
    const float* vb = g_s + b * 512;
    float acc = 0.f;
    for (int k = lane; k < 512; k += 32) acc += W[(size_t)m * 512 + k] * vb[k];
    #pragma unroll
    for (int off = 16; off; off >>= 1) acc += __shfl_down_sync(0xffffffffu, acc, off);
    if (lane == 0) o[b * 512 + m] = acc;
}

// bo2 = Wo by + bo
__global__ void __launch_bounds__(256) gemv_bo(
    const float* __restrict__ Wo, const float* __restrict__ bo)
{
    const int b = blockIdx.y, m = blockIdx.x * 8 + (threadIdx.x >> 5), lane = threadIdx.x & 31;
    const float* vb = g_by + b * 512;
    float acc = 0.f;
    for (int k = lane; k < 512; k += 32) acc += Wo[(size_t)m * 512 + k] * vb[k];
    #pragma unroll
    for (int off = 16; off; off >>= 1) acc += __shfl_down_sync(0xffffffffu, acc, off);
    if (lane == 0) g_bo2[b * 512 + m] = acc + bo[m];
}

// L[h][h'] = (sum_c U[hd,c]*Wk[h'd,c] + bias terms)/8, softmax, *gamma
__global__ void __launch_bounds__(256) lsoftmax(
    const float* __restrict__ Wk, const float* __restrict__ bq,
    const float* __restrict__ bk, const float* __restrict__ gamma)
{
    const int d = blockIdx.x, b = blockIdx.y;
    const int t = threadIdx.x, pair = t >> 2, h = pair >> 3, hp = pair & 7, cs = t & 3;
    const float* Ur = g_U + ((size_t)b * 512 + h * 64 + d) * 512;
    const float* Kr = Wk + (size_t)(hp * 64 + d) * 512;
    float acc = 0.f;
    for (int cc = cs; cc < 512; cc += 4) acc += Ur[cc] * Kr[cc];
    acc += __shfl_down_sync(0xffffffffu, acc, 2);
    acc += __shfl_down_sync(0xffffffffu, acc, 1);
    __shared__ float sL[64];
    if (cs == 0) {
        const int qi = h * 64 + d, ki = hp * 64 + d;
        const float Lv = acc + bq[qi] * g_ks[b * 512 + ki] + bk[ki] * g_qs[b * 512 + qi]
                       + 4096.f * bq[qi] * bk[ki];
        sL[pair] = Lv * 0.125f;
    }
    __syncthreads();
    if (t < 8) {
        float m = -INFINITY;
        #pragma unroll
        for (int j = 0; j < 8; j++) m = fmaxf(m, sL[t * 8 + j]);
        float e[8], ssum = 0.f;
        #pragma unroll
        for (int j = 0; j < 8; j++) { e[j] = expf(sL[t * 8 + j] - m); ssum += e[j]; }
        const float sc = gamma[0] / ssum;
        #pragma unroll
        for (int j = 0; j < 8; j++) g_A[b * 4096 + d * 64 + t * 8 + j] = e[j] * sc;
    }
}

// Wy[b][h*64+d][c] = sum_j (gA)[d,h,j]*Wv[j*64+d][c]; by = sum_j (gA)*bv
__global__ void __launch_bounds__(256) build_wy(
    const float* __restrict__ Wv, const float* __restrict__ bv)
{
    const int d = blockIdx.x, b = blockIdx.y, t = threadIdx.x;
    __shared__ float a[64];
    if (t < 64) a[t] = g_A[b * 4096 + d * 64 + t];
    __syncthreads();
    if (t < 8) {
        float s = 0.f;
        #pragma unroll
        for (int j = 0; j < 8; j++) s += a[t * 8 + j] * bv[j * 64 + d];
        g_by[b * 512 + t * 64 + d] = s;
    }
    for (int cc = t; cc < 512; cc += 256) {
        float v[8];
        #pragma unroll
        for (int j = 0; j < 8; j++) v[j] = Wv[(size_t)(j * 64 + d) * 512 + cc];
        #pragma unroll
        for (int hh = 0; hh < 8; hh++) {
            float y = 0.f;
            #pragma unroll
            for (int j = 0; j < 8; j++) y += a[hh * 8 + j] * v[j];
            g_Wyh[(size_t)b * CCH * CCH + (size_t)(hh * 64 + d) * 512 + cc] = __float2half_rn(y);
        }
    }
}

// ---------------------------------------------------------------------------
extern "C" void kernel_launch(void* const* d_in, const int* in_sizes, int n_in,
                              void* d_out, int out_size)
{
    const float* x  = (const float*)d_in[0];
    const float* Wq = (const float*)d_in[1];
    const float* bq = (const float*)d_in[2];
    const float* Wk = (const float*)d_in[3];
    const float* bk = (const float*)d_in[4];
    const float* Wv = (const float*)d_in[5];
    const float* bv = (const float*)d_in[6];
    const float* Wo = (const float*)d_in[7];
    const float* bo = (const float*)d_in[8];
    const float* gm = (const float*)d_in[9];
    float* out = (float*)d_out;

    __half *Xh, *Xl, *XTh, *XTl, *Wh, *Wl, *Gh, *Gl, *Wyh, *Mh;
    float *GpP, *UP, *bo2P;
    cudaGetSymbolAddress((void**)&Xh, g_Xh);   cudaGetSymbolAddress((void**)&Xl, g_Xl);
    cudaGetSymbolAddress((void**)&XTh, g_XTh); cudaGetSymbolAddress((void**)&XTl, g_XTl);
    cudaGetSymbolAddress((void**)&Wh, g_Wh);   cudaGetSymbolAddress((void**)&Wl, g_Wl);
    cudaGetSymbolAddress((void**)&Gh, g_Gh);   cudaGetSymbolAddress((void**)&Gl, g_Gl);
    cudaGetSymbolAddress((void**)&Wyh, g_Wyh); cudaGetSymbolAddress((void**)&Mh, g_Mh);
    cudaGetSymbolAddress((void**)&GpP, g_Gp);  cudaGetSymbolAddress((void**)&UP, g_U);
    cudaGetSymbolAddress((void**)&bo2P, g_bo2);

    static bool attr = false;
    if (!attr) {
        cudaFuncSetAttribute(hgemm<false, true,  true,  false>, cudaFuncAttributeMaxDynamicSharedMemorySize, SMEM_FULL);
        cudaFuncSetAttribute(hgemm<false, true,  false, false>, cudaFuncAttributeMaxDynamicSharedMemorySize, SMEM_FULL);
        cudaFuncSetAttribute(hgemm<false, false, false, true >, cudaFuncAttributeMaxDynamicSharedMemorySize, SMEM_LITE);
        cudaFuncSetAttribute(hgemm<true,  false, false, false>, cudaFuncAttributeMaxDynamicSharedMemorySize, SMEM_LITE);
        attr = true;
    }

    const size_t WS = (size_t)CCH * CCH;
    const size_t XS = (size_t)CCH * NPIX;

    zero_s<<<8, 512>>>();
    prep_x<<<(unsigned)((size_t)BATCH * XS / 2048), 256>>>(x);
    prep_xT<<<dim3(NPIX / 32, CCH / 32, BATCH), dim3(32, 8)>>>(x);
    prep_w<<<dim3(CCH * CCH / 256, 4), 256>>>(Wq, Wk, Wv, Wo);
    gemv_qk<<<dim3(64, BATCH, 2), 256>>>(Wq, Wk);

    // Gram: G_b = x x^T, upper-triangle tiles, split-K4 (3-pass)
    hgemm<false, true, true, false><<<dim3(10, 1, 8 * SPLITK), 512, SMEM_FULL>>>(
        Xh, Xl, XTh, XTl, nullptr, nullptr, GpP,
        512, NPIX, 128 / SPLITK, XS, XS, 0, (size_t)BATCH * WS);
    splitG<<<dim3(16, 16, BATCH), dim3(32, 8)>>>();

    // U_b = Wq G_b (3-pass)
    hgemm<false, true, false, false><<<dim3(4, 4, BATCH), 512, SMEM_FULL>>>(
        Wh + 0 * WS, Wl + 0 * WS, Gh, Gl, nullptr, nullptr, UP,
        512, 512, 16, 0, WS, 0, 0);

    lsoftmax<<<dim3(64, BATCH), 256>>>(Wk, bq, bk, gm);
    build_wy<<<dim3(64, BATCH), 256>>>(Wv, bv);
    gemv_bo<<<dim3(64, BATCH), 256>>>(Wo, bo);

    // M_b = Wo * Wy_b (1-pass), fp16 output directly
    hgemm<false, false, false, true><<<dim3(4, 4, BATCH), 512, SMEM_LITE>>>(
        Wh + 3 * WS, nullptr, Wyh, nullptr, nullptr, nullptr, Mh,
        512, 512, 16, 0, WS, 0, 0);

    // out = M_b x + bo2_b + x (1-pass)
    hgemm<true, false, false, false><<<dim3(NPIX / 128, 4, BATCH), 512, SMEM_LITE>>>(
        Mh, nullptr, Xh, nullptr, bo2P, x, out,
        NPIX, 512, 16, WS, XS, 512, 0);
}

// round 12
// speedup vs baseline: 1.0380x; 1.0380x over previous
#include <cuda_runtime.h>
#include <cuda_fp16.h>
#include <math.h>
#include <stdint.h>

#define CCH   512
#define NPIX  4096
#define BATCH 8
#define SPLITK 8

// ---------------- scratch ----------------
__device__ __half g_Xh[(size_t)BATCH * CCH * NPIX];
__device__ __half g_Xl[(size_t)BATCH * CCH * NPIX];
__device__ __half g_XTh[(size_t)BATCH * CCH * NPIX];
__device__ __half g_XTl[(size_t)BATCH * CCH * NPIX];
__device__ __half g_Wh[4 * CCH * CCH];
__device__ __half g_Wl[4 * CCH * CCH];
__device__ float  g_s [BATCH * CCH];
__device__ float  g_qs[BATCH * CCH];
__device__ float  g_ks[BATCH * CCH];
__device__ float  g_by[BATCH * CCH];
__device__ float  g_bo2[BATCH * CCH];
__device__ float  g_Gp[SPLITK][(size_t)BATCH * CCH * CCH];  // split-K partials
__device__ __half g_Gh[(size_t)BATCH * CCH * CCH];
__device__ __half g_Gl[(size_t)BATCH * CCH * CCH];
__device__ float  g_U [(size_t)BATCH * CCH * CCH];
__device__ __half g_Wyh[(size_t)BATCH * CCH * CCH];
__device__ __half g_Mh[(size_t)BATCH * CCH * CCH];

__constant__ int c_pm[10] = {0,0,0,0,1,1,1,2,2,3};
__constant__ int c_pn[10] = {0,1,2,3,1,2,3,2,3,3};

// ---------------- helpers ----------------
__device__ __forceinline__ uint32_t smem_u32(const void* p) {
    uint32_t a;
    asm("{ .reg .u64 t; cvta.to.shared.u64 t, %1; cvt.u32.u64 %0, t; }" : "=r"(a) : "l"(p));
    return a;
}
__device__ __forceinline__ void cpasync16(uint32_t dst, const void* src) {
    asm volatile("cp.async.cg.shared.global [%0], [%1], 16;" :: "r"(dst), "l"(src));
}
#define CP_COMMIT() asm volatile("cp.async.commit_group;" ::: "memory")
template<int N> __device__ __forceinline__ void cp_wait() {
    asm volatile("cp.async.wait_group %0;" :: "n"(N) : "memory");
}
__device__ __forceinline__ void ldsm4(uint32_t* r, uint32_t addr) {
    asm volatile("ldmatrix.sync.aligned.m8n8.x4.shared.b16 {%0,%1,%2,%3}, [%4];"
                 : "=r"(r[0]), "=r"(r[1]), "=r"(r[2]), "=r"(r[3]) : "r"(addr));
}
__device__ __forceinline__ void ldsm4t(uint32_t* r, uint32_t addr) {
    asm volatile("ldmatrix.sync.aligned.m8n8.x4.trans.shared.b16 {%0,%1,%2,%3}, [%4];"
                 : "=r"(r[0]), "=r"(r[1]), "=r"(r[2]), "=r"(r[3]) : "r"(addr));
}
__device__ __forceinline__ void mma16816(float* c, const uint32_t* a, uint32_t b0, uint32_t b1) {
    asm volatile("mma.sync.aligned.m16n8k16.row.col.f32.f16.f16.f32 "
                 "{%0,%1,%2,%3}, {%4,%5,%6,%7}, {%8,%9}, {%0,%1,%2,%3};"
                 : "+f"(c[0]), "+f"(c[1]), "+f"(c[2]), "+f"(c[3])
                 : "r"(a[0]), "r"(a[1]), "r"(a[2]), "r"(a[3]), "r"(b0), "r"(b1));
}

#define A_ST 40
#define B_ST 136
#define A_MAT (128 * A_ST)
#define B_MAT (32 * B_ST)
#define STG_FULL (2 * A_MAT + 2 * B_MAT)
#define STG_LITE (A_MAT + B_MAT)
#define SMEM_FULL (4 * STG_FULL * 2)
#define SMEM_LITE (4 * STG_LITE * 2)

// ---------------------------------------------------------------------------
// hgemm (R10 inner loop — one k16 live, 96 regs)
// ---------------------------------------------------------------------------
template<bool RESID, bool FULL, bool TRI, bool HOUT>
__global__ void __launch_bounds__(512, 1) hgemm(
    const __half* __restrict__ Whg, const __half* __restrict__ Wlg,
    const __half* __restrict__ Xhg, const __half* __restrict__ Xlg,
    const float* __restrict__ bias, const float* __restrict__ resid,
    void* __restrict__ out,
    int npix, int kfull, int nch,
    size_t wstride, size_t xstride, int bstride, size_t oslice)
{
    extern __shared__ __half sm[];
    const uint32_t sb = smem_u32(sm);
    constexpr int STG = FULL ? STG_FULL : STG_LITE;
    constexpr int OFF_AH = 0, OFF_AL = A_MAT;
    constexpr int OFF_BH = FULL ? 2 * A_MAT : A_MAT;
    constexpr int OFF_BL = 2 * A_MAT + B_MAT;

    const int tid = threadIdx.x, lane = tid & 31, wid = tid >> 5;
    const int wm = wid >> 2, wn = wid & 3;
    const int b = blockIdx.z & 7, ksl = blockIdx.z >> 3;
    const int m0 = (TRI ? c_pm[blockIdx.x] : (int)blockIdx.y) * 128;
    const int n0 = (TRI ? c_pn[blockIdx.x] : (int)blockIdx.x) * 128;
    const int kg0 = ksl * nch * 32;
    const __half* Wb  = Whg + (size_t)b * wstride;
    const __half* Wlb = FULL ? Wlg + (size_t)b * wstride : nullptr;
    const __half* Bhp = Xhg + (size_t)b * xstride;
    const __half* Blp = FULL ? Xlg + (size_t)b * xstride : nullptr;
    const size_t obase = (size_t)ksl * oslice;

    const int ar = tid >> 2, ak = (tid & 3) * 8;
    const int br = tid >> 4, bn = (tid & 15) * 8;
    const int quad = lane >> 3, r8 = lane & 7;
    const int qlow = (quad & 1) * 8, qhi = (quad >> 1) * 8;

    float c[2][4][4];
    #pragma unroll
    for (int i = 0; i < 2; i++)
        #pragma unroll
        for (int j = 0; j < 4; j++)
            #pragma unroll
            for (int e = 0; e < 4; e++) c[i][j][e] = 0.f;

    auto issue = [&](int s, int ch) {
        const int k0 = kg0 + ch * 32;
        const uint32_t st = sb + 2 * (s * STG);
        cpasync16(st + 2 * (OFF_AH + ar * A_ST + ak), Wb  + (size_t)(m0 + ar) * kfull + k0 + ak);
        cpasync16(st + 2 * (OFF_BH + br * B_ST + bn), Bhp + (size_t)(k0 + br) * npix + n0 + bn);
        if (FULL) {
            cpasync16(st + 2 * (OFF_AL + ar * A_ST + ak), Wlb + (size_t)(m0 + ar) * kfull + k0 + ak);
            cpasync16(st + 2 * (OFF_BL + br * B_ST + bn), Blp + (size_t)(k0 + br) * npix + n0 + bn);
        }
    };

    issue(0, 0); CP_COMMIT();
    issue(1, 1); CP_COMMIT();

    for (int ch = 0; ch < nch; ch++) {
        const int s = ch & 3;
        if (ch + 2 < nch) { issue((ch + 2) & 3, ch + 2); CP_COMMIT(); }
        if (ch + 2 < nch)      cp_wait<2>();
        else if (ch + 1 < nch) cp_wait<1>();
        else                   cp_wait<0>();
        __syncthreads();

        const uint32_t sbase = sb + 2 * (s * STG);
        #pragma unroll
        for (int k16 = 0; k16 < 2; k16++) {
            uint32_t ah[2][4], al[2][4], bh[2][4], bl[2][4];
            #pragma unroll
            for (int mi = 0; mi < 2; mi++) {
                const uint32_t off = 2 * ((uint32_t)(wm * 32 + mi * 16 + r8 + qlow) * A_ST + k16 * 16 + qhi);
                ldsm4(ah[mi], sbase + 2 * OFF_AH + off);
                if (FULL) ldsm4(al[mi], sbase + 2 * OFF_AL + off);
            }
            #pragma unroll
            for (int ni = 0; ni < 2; ni++) {
                const uint32_t off = 2 * ((uint32_t)(k16 * 16 + r8 + qlow) * B_ST + wn * 32 + ni * 16 + qhi);
                ldsm4t(bh[ni], sbase + 2 * OFF_BH + off);
                if (FULL) ldsm4t(bl[ni], sbase + 2 * OFF_BL + off);
            }
            #pragma unroll
            for (int mi = 0; mi < 2; mi++)
                #pragma unroll
                for (int j = 0; j < 4; j++) {
                    const int ni = j >> 1, ss = (j & 1) * 2;
                    mma16816(c[mi][j], ah[mi], bh[ni][ss], bh[ni][ss + 1]);
                    if (FULL) {
                        mma16816(c[mi][j], ah[mi], bl[ni][ss], bl[ni][ss + 1]);
                        mma16816(c[mi][j], al[mi], bh[ni][ss], bh[ni][ss + 1]);
                    }
                }
        }
        __syncthreads();
    }

    #pragma unroll
    for (int mi = 0; mi < 2; mi++) {
        #pragma unroll
        for (int rr = 0; rr < 2; rr++) {
            const int m = m0 + wm * 32 + mi * 16 + (lane >> 2) + rr * 8;
            const float bi = bias ? __ldg(&bias[b * bstride + m]) : 0.f;
            const size_t rowoff = ((size_t)b * CCH + m) * npix + n0 + wn * 32 + (lane & 3) * 2;
            #pragma unroll
            for (int j = 0; j < 4; j++) {
                float2 v;
                v.x = c[mi][j][rr * 2 + 0] + bi;
                v.y = c[mi][j][rr * 2 + 1] + bi;
                if (RESID) {
                    float2 r = *(const float2*)&resid[rowoff + j * 8];
                    v.x += r.x; v.y += r.y;
                }
                if (HOUT) {
                    __half2 hv = __halves2half2(__float2half_rn(v.x), __float2half_rn(v.y));
                    *(__half2*)((__half*)out + obase + rowoff + j * 8) = hv;
                } else {
                    *(float2*)((float*)out + obase + rowoff + j * 8) = v;
                }
            }
        }
    }
}

// ---------------------------------------------------------------------------
__global__ void zero_s() { g_s[blockIdx.x * 512 + threadIdx.x] = 0.f; }

// prep_x: coalesced split fp32 -> fp16 hi/lo + row-sum atomic
__global__ void __launch_bounds__(256) prep_x(const float* __restrict__ src) {
    __shared__ float red[256];
    const size_t i = ((size_t)blockIdx.x * 256 + threadIdx.x) * 8;
    float4 v0 = *(const float4*)&src[i];
    float4 v1 = *(const float4*)&src[i + 4];
    const float v[8] = {v0.x, v0.y, v0.z, v0.w, v1.x, v1.y, v1.z, v1.w};
    __half h[8], l[8];
    float ps = 0.f;
    #pragma unroll
    for (int e = 0; e < 8; e++) {
        h[e] = __float2half_rn(v[e]);
        l[e] = __float2half_rn(v[e] - __half2float(h[e]));
        ps += v[e];
    }
    *(uint4*)&g_Xh[i] = *(const uint4*)h;
    *(uint4*)&g_Xl[i] = *(const uint4*)l;
    red[threadIdx.x] = ps; __syncthreads();
    for (int o = 128; o; o >>= 1) {
        if (threadIdx.x < o) red[threadIdx.x] += red[threadIdx.x + o];
        __syncthreads();
    }
    if (threadIdx.x == 0) atomicAdd(&g_s[blockIdx.x >> 1], red[0]);
}

// transpose + split, sourcing the (hi,lo) halves (32 MiB read instead of 64).
// v = hi + lo re-splits to the identical (hi, lo) pair.
__global__ void __launch_bounds__(256) prep_xT() {
    __shared__ float s[32][33];
    const int n0 = blockIdx.x * 32, c0 = blockIdx.y * 32, b = blockIdx.z;
    const int tx = threadIdx.x, ty = threadIdx.y;
    #pragma unroll
    for (int i = 0; i < 4; i++) {
        const size_t idx = ((size_t)(b * CCH + c0 + ty + 8 * i)) * NPIX + n0 + tx;
        s[ty + 8 * i][tx] = __half2float(g_Xh[idx]) + __half2float(g_Xl[idx]);
    }
    __syncthreads();
    #pragma unroll
    for (int i = 0; i < 4; i++) {
        const float v = s[tx][ty + 8 * i];
        const __half hi = __float2half_rn(v);
        const size_t idx = ((size_t)b * NPIX + n0 + ty + 8 * i) * CCH + c0 + tx;
        g_XTh[idx] = hi;
        g_XTl[idx] = __float2half_rn(v - __half2float(hi));
    }
}

__global__ void __launch_bounds__(256) prep_w(
    const float* __restrict__ Wq, const float* __restrict__ Wk,
    const float* __restrict__ Wv, const float* __restrict__ Wo)
{
    const int m = blockIdx.y;
    const size_t t = (size_t)blockIdx.x * 256 + threadIdx.x;
    const float* W = (m == 0) ? Wq : (m == 1) ? Wk : (m == 2) ? Wv : Wo;
    const float v = W[t];
    const __half h = __float2half_rn(v);
    g_Wh[(size_t)m * CCH * CCH + t] = h;
    g_Wl[(size_t)m * CCH * CCH + t] = __float2half_rn(v - __half2float(h));
}

// sum SPLITK split-K partials, mirror lower triangle, split to fp16
__global__ void __launch_bounds__(256) splitG() {
    __shared__ float s[32][33];
    const int ti = blockIdx.x, tj = blockIdx.y, b = blockIdx.z;
    const int tx = threadIdx.x, ty = threadIdx.y;
    const size_t base = (size_t)b * CCH * CCH;
    const bool swap = (ti >> 2) > (tj >> 2);
    if (!swap) {
        #pragma unroll
        for (int k = 0; k < 4; k++) {
            const int r = ti * 32 + ty + 8 * k, cc = tj * 32 + tx;
            const size_t o = base + (size_t)r * CCH + cc;
            float v = 0.f;
            #pragma unroll
            for (int p = 0; p < SPLITK; p++) v += g_Gp[p][o];
            const __half hi = __float2half_rn(v);
            g_Gh[o] = hi; g_Gl[o] = __float2half_rn(v - __half2float(hi));
        }
    } else {
        #pragma unroll
        for (int k = 0; k < 4; k++) {
            const int r = tj * 32 + ty + 8 * k, cc = ti * 32 + tx;
            const size_t o = base + (size_t)r * CCH + cc;
            float v = 0.f;
            #pragma unroll
            for (int p = 0; p < SPLITK; p++) v += g_Gp[p][o];
            s[ty + 8 * k][tx] = v;
        }
        __syncthreads();
        #pragma unroll
        for (int k = 0; k < 4; k++) {
            const int r = ti * 32 + ty + 8 * k, cc = tj * 32 + tx;
            const float v = s[tx][ty + 8 * k];
            const __half hi = __float2half_rn(v);
            const size_t o = base + (size_t)r * CCH + cc;
            g_Gh[o] = hi; g_Gl[o] = __float2half_rn(v - __half2float(hi));
        }
    }
}

// qs = Wq s ; ks = Wk s  (grid.z selects matrix)
__global__ void __launch_bounds__(256) gemv_qk(
    const float* __restrict__ Wq, const float* __restrict__ Wk)
{
    const int b = blockIdx.y, m = blockIdx.x * 8 + (threadIdx.x >> 5), lane = threadIdx.x & 31;
    const float* W = blockIdx.z ? Wk : Wq;
    float* o = blockIdx.z ? g_ks : g_qs;
    const float* vb = g_s + b * 512;
    float acc = 0.f;
    for (int k = lane; k < 512; k += 32) acc += W[(size_t)m * 512 + k] * vb[k];
    #pragma unroll
    for (int off = 16; off; off >>= 1) acc += __shfl_down_sync(0xffffffffu, acc, off);
    if (lane == 0) o[b * 512 + m] = acc;
}

// bo2 = Wo by + bo
__global__ void __launch_bounds__(256) gemv_bo(
    const float* __restrict__ Wo, const float* __restrict__ bo)
{
    const int b = blockIdx.y, m = blockIdx.x * 8 + (threadIdx.x >> 5), lane = threadIdx.x & 31;
    const float* vb = g_by + b * 512;
    float acc = 0.f;
    for (int k = lane; k < 512; k += 32) acc += Wo[(size_t)m * 512 + k] * vb[k];
    #pragma unroll
    for (int off = 16; off; off >>= 1) acc += __shfl_down_sync(0xffffffffu, acc, off);
    if (lane == 0) g_bo2[b * 512 + m] = acc + bo[m];
}

// Fused: softmax(L(d)) (gamma-folded, kept in SMEM) then Wy rows + by.
// grid (64 d, BATCH), 256 threads.
__global__ void __launch_bounds__(256) lsoftmax_wy(
    const float* __restrict__ Wk, const float* __restrict__ bq,
    const float* __restrict__ bk, const float* __restrict__ gamma,
    const float* __restrict__ Wv, const float* __restrict__ bv)
{
    const int d = blockIdx.x, b = blockIdx.y;
    const int t = threadIdx.x, pair = t >> 2, h = pair >> 3, hp = pair & 7, cs = t & 3;

    // --- logits ---
    const float* Ur = g_U + ((size_t)b * 512 + h * 64 + d) * 512;
    const float* Kr = Wk + (size_t)(hp * 64 + d) * 512;
    float acc = 0.f;
    for (int cc = cs; cc < 512; cc += 4) acc += Ur[cc] * Kr[cc];
    acc += __shfl_down_sync(0xffffffffu, acc, 2);
    acc += __shfl_down_sync(0xffffffffu, acc, 1);
    __shared__ float sL[64];
    __shared__ float a_s[64];
    if (cs == 0) {
        const int qi = h * 64 + d, ki = hp * 64 + d;
        const float Lv = acc + bq[qi] * g_ks[b * 512 + ki] + bk[ki] * g_qs[b * 512 + qi]
                       + 4096.f * bq[qi] * bk[ki];
        sL[pair] = Lv * 0.125f;
    }
    __syncthreads();
    // --- softmax (gamma folded) into SMEM ---
    if (t < 8) {
        float m = -INFINITY;
        #pragma unroll
        for (int j = 0; j < 8; j++) m = fmaxf(m, sL[t * 8 + j]);
        float e[8], ssum = 0.f;
        #pragma unroll
        for (int j = 0; j < 8; j++) { e[j] = expf(sL[t * 8 + j] - m); ssum += e[j]; }
        const float sc = gamma[0] / ssum;
        #pragma unroll
        for (int j = 0; j < 8; j++) a_s[t * 8 + j] = e[j] * sc;
    }
    __syncthreads();
    // --- by + Wy rows ---
    if (t < 8) {
        float s = 0.f;
        #pragma unroll
        for (int j = 0; j < 8; j++) s += a_s[t * 8 + j] * bv[j * 64 + d];
        g_by[b * 512 + t * 64 + d] = s;
    }
    for (int cc = t; cc < 512; cc += 256) {
        float v[8];
        #pragma unroll
        for (int j = 0; j < 8; j++) v[j] = Wv[(size_t)(j * 64 + d) * 512 + cc];
        #pragma unroll
        for (int hh = 0; hh < 8; hh++) {
            float y = 0.f;
            #pragma unroll
            for (int j = 0; j < 8; j++) y += a_s[hh * 8 + j] * v[j];
            g_Wyh[(size_t)b * CCH * CCH + (size_t)(hh * 64 + d) * 512 + cc] = __float2half_rn(y);
        }
    }
}

// ---------------------------------------------------------------------------
extern "C" void kernel_launch(void* const* d_in, const int* in_sizes, int n_in,
                              void* d_out, int out_size)
{
    const float* x  = (const float*)d_in[0];
    const float* Wq = (const float*)d_in[1];
    const float* bq = (const float*)d_in[2];
    const float* Wk = (const float*)d_in[3];
    const float* bk = (const float*)d_in[4];
    const float* Wv = (const float*)d_in[5];
    const float* bv = (const float*)d_in[6];
    const float* Wo = (const float*)d_in[7];
    const float* bo = (const float*)d_in[8];
    const float* gm = (const float*)d_in[9];
    float* out = (float*)d_out;

    __half *Xh, *Xl, *XTh, *XTl, *Wh, *Wl, *Gh, *Gl, *Wyh, *Mh;
    float *GpP, *UP, *bo2P;
    cudaGetSymbolAddress((void**)&Xh, g_Xh);   cudaGetSymbolAddress((void**)&Xl, g_Xl);
    cudaGetSymbolAddress((void**)&XTh, g_XTh); cudaGetSymbolAddress((void**)&XTl, g_XTl);
    cudaGetSymbolAddress((void**)&Wh, g_Wh);   cudaGetSymbolAddress((void**)&Wl, g_Wl);
    cudaGetSymbolAddress((void**)&Gh, g_Gh);   cudaGetSymbolAddress((void**)&Gl, g_Gl);
    cudaGetSymbolAddress((void**)&Wyh, g_Wyh); cudaGetSymbolAddress((void**)&Mh, g_Mh);
    cudaGetSymbolAddress((void**)&GpP, g_Gp);  cudaGetSymbolAddress((void**)&UP, g_U);
    cudaGetSymbolAddress((void**)&bo2P, g_bo2);

    static bool attr = false;
    if (!attr) {
        cudaFuncSetAttribute(hgemm<false, true,  true,  false>, cudaFuncAttributeMaxDynamicSharedMemorySize, SMEM_FULL);
        cudaFuncSetAttribute(hgemm<false, true,  false, false>, cudaFuncAttributeMaxDynamicSharedMemorySize, SMEM_FULL);
        cudaFuncSetAttribute(hgemm<false, false, false, true >, cudaFuncAttributeMaxDynamicSharedMemorySize, SMEM_LITE);
        cudaFuncSetAttribute(hgemm<true,  false, false, false>, cudaFuncAttributeMaxDynamicSharedMemorySize, SMEM_LITE);
        attr = true;
    }

    const size_t WS = (size_t)CCH * CCH;
    const size_t XS = (size_t)CCH * NPIX;

    zero_s<<<8, 512>>>();
    prep_x<<<(unsigned)((size_t)BATCH * XS / 2048), 256>>>(x);
    prep_xT<<<dim3(NPIX / 32, CCH / 32, BATCH), dim3(32, 8)>>>();
    prep_w<<<dim3(CCH * CCH / 256, 4), 256>>>(Wq, Wk, Wv, Wo);
    gemv_qk<<<dim3(64, BATCH, 2), 256>>>(Wq, Wk);

    // Gram: G_b = x x^T, upper-triangle tiles, split-K8 (3-pass)
    hgemm<false, true, true, false><<<dim3(10, 1, 8 * SPLITK), 512, SMEM_FULL>>>(
        Xh, Xl, XTh, XTl, nullptr, nullptr, GpP,
        512, NPIX, 128 / SPLITK, XS, XS, 0, (size_t)BATCH * WS);
    splitG<<<dim3(16, 16, BATCH), dim3(32, 8)>>>();

    // U_b = Wq G_b (3-pass)
    hgemm<false, true, false, false><<<dim3(4, 4, BATCH), 512, SMEM_FULL>>>(
        Wh + 0 * WS, Wl + 0 * WS, Gh, Gl, nullptr, nullptr, UP,
        512, 512, 16, 0, WS, 0, 0);

    lsoftmax_wy<<<dim3(64, BATCH), 256>>>(Wk, bq, bk, gm, Wv, bv);
    gemv_bo<<<dim3(64, BATCH), 256>>>(Wo, bo);

    // M_b = Wo * Wy_b (1-pass), fp16 output directly
    hgemm<false, false, false, true><<<dim3(4, 4, BATCH), 512, SMEM_LITE>>>(
        Wh + 3 * WS, nullptr, Wyh, nullptr, nullptr, nullptr, Mh,
        512, 512, 16, 0, WS, 0, 0);

    // out = M_b x + bo2_b + x (1-pass)
    hgemm<true, false, false, false><<<dim3(NPIX / 128, 4, BATCH), 512, SMEM_LITE>>>(
        Mh, nullptr, Xh, nullptr, bo2P, x, out,
        NPIX, 512, 16, WS, XS, 512, 0);
}

// round 13
// speedup vs baseline: 1.1405x; 1.0988x over previous
#include <cuda_runtime.h>
#include <cuda_fp16.h>
#include <math.h>
#include <stdint.h>

#define CCH   512
#define NPIX  4096
#define BATCH 8
#define SPLITK 8

// ---------------- scratch ----------------
__device__ __half g_Xh[(size_t)BATCH * CCH * NPIX];
__device__ __half g_Xl[(size_t)BATCH * CCH * NPIX];
__device__ __half g_XTh[(size_t)BATCH * CCH * NPIX];
__device__ __half g_XTl[(size_t)BATCH * CCH * NPIX];
__device__ __half g_Wh[4 * CCH * CCH];
__device__ __half g_Wl[4 * CCH * CCH];
__device__ float  g_s [BATCH * CCH];
__device__ float  g_qs[BATCH * CCH];
__device__ float  g_ks[BATCH * CCH];
__device__ float  g_by[BATCH * CCH];
__device__ float  g_bo2[BATCH * CCH];
__device__ float  g_Gp[SPLITK][(size_t)BATCH * CCH * CCH];  // split-K partials
__device__ __half g_Gh[(size_t)BATCH * CCH * CCH];
__device__ __half g_Gl[(size_t)BATCH * CCH * CCH];
__device__ float  g_U [(size_t)BATCH * CCH * CCH];
__device__ __half g_Wyh[(size_t)BATCH * CCH * CCH];
__device__ __half g_Mh[(size_t)BATCH * CCH * CCH];

__constant__ int c_pm[10] = {0,0,0,0,1,1,1,2,2,3};
__constant__ int c_pn[10] = {0,1,2,3,1,2,3,2,3,3};

// ---------------- helpers ----------------
__device__ __forceinline__ uint32_t smem_u32(const void* p) {
    uint32_t a;
    asm("{ .reg .u64 t; cvta.to.shared.u64 t, %1; cvt.u32.u64 %0, t; }" : "=r"(a) : "l"(p));
    return a;
}
__device__ __forceinline__ void cpasync16(uint32_t dst, const void* src) {
    asm volatile("cp.async.cg.shared.global [%0], [%1], 16;" :: "r"(dst), "l"(src));
}
#define CP_COMMIT() asm volatile("cp.async.commit_group;" ::: "memory")
template<int N> __device__ __forceinline__ void cp_wait() {
    asm volatile("cp.async.wait_group %0;" :: "n"(N) : "memory");
}
__device__ __forceinline__ void ldsm4(uint32_t* r, uint32_t addr) {
    asm volatile("ldmatrix.sync.aligned.m8n8.x4.shared.b16 {%0,%1,%2,%3}, [%4];"
                 : "=r"(r[0]), "=r"(r[1]), "=r"(r[2]), "=r"(r[3]) : "r"(addr));
}
__device__ __forceinline__ void ldsm4t(uint32_t* r, uint32_t addr) {
    asm volatile("ldmatrix.sync.aligned.m8n8.x4.trans.shared.b16 {%0,%1,%2,%3}, [%4];"
                 : "=r"(r[0]), "=r"(r[1]), "=r"(r[2]), "=r"(r[3]) : "r"(addr));
}
__device__ __forceinline__ void mma16816(float* c, const uint32_t* a, uint32_t b0, uint32_t b1) {
    asm volatile("mma.sync.aligned.m16n8k16.row.col.f32.f16.f16.f32 "
                 "{%0,%1,%2,%3}, {%4,%5,%6,%7}, {%8,%9}, {%0,%1,%2,%3};"
                 : "+f"(c[0]), "+f"(c[1]), "+f"(c[2]), "+f"(c[3])
                 : "r"(a[0]), "r"(a[1]), "r"(a[2]), "r"(a[3]), "r"(b0), "r"(b1));
}

#define A_ST 40
#define B_ST 136
#define A_MAT (128 * A_ST)
#define B_MAT (32 * B_ST)
#define STG_FULL (2 * A_MAT + 2 * B_MAT)
#define STG_LITE (A_MAT + B_MAT)
#define NSTAGE 5
#define SMEM_FULL (NSTAGE * STG_FULL * 2)   // 189440 B
#define SMEM_LITE (NSTAGE * STG_LITE * 2)   //  94720 B

// ---------------------------------------------------------------------------
// hgemm: out[b][m][n] = sum_k W[m,k] * X[b][k][n] (+bias[b][m]) (+resid)
// FULL: 3-pass double-fp16. TRI: upper-triangle tile remap. HOUT: fp16 out.
// 5-stage cp.async pipeline, issue-ahead-2, ONE barrier per K-chunk:
// write target stage (ch+2)%5 was last read at chunk ch-3, which completed
// before the leading sync of chunk ch-1, so no trailing barrier is needed.
// ---------------------------------------------------------------------------
template<bool RESID, bool FULL, bool TRI, bool HOUT>
__global__ void __launch_bounds__(512, 1) hgemm(
    const __half* __restrict__ Whg, const __half* __restrict__ Wlg,
    const __half* __restrict__ Xhg, const __half* __restrict__ Xlg,
    const float* __restrict__ bias, const float* __restrict__ resid,
    void* __restrict__ out,
    int npix, int kfull, int nch,
    size_t wstride, size_t xstride, int bstride, size_t oslice)
{
    extern __shared__ __half sm[];
    const uint32_t sb = smem_u32(sm);
    constexpr int STG = FULL ? STG_FULL : STG_LITE;
    constexpr int OFF_AH = 0, OFF_AL = A_MAT;
    constexpr int OFF_BH = FULL ? 2 * A_MAT : A_MAT;
    constexpr int OFF_BL = 2 * A_MAT + B_MAT;

    const int tid = threadIdx.x, lane = tid & 31, wid = tid >> 5;
    const int wm = wid >> 2, wn = wid & 3;
    const int b = blockIdx.z & 7, ksl = blockIdx.z >> 3;
    const int m0 = (TRI ? c_pm[blockIdx.x] : (int)blockIdx.y) * 128;
    const int n0 = (TRI ? c_pn[blockIdx.x] : (int)blockIdx.x) * 128;
    const int kg0 = ksl * nch * 32;
    const __half* Wb  = Whg + (size_t)b * wstride;
    const __half* Wlb = FULL ? Wlg + (size_t)b * wstride : nullptr;
    const __half* Bhp = Xhg + (size_t)b * xstride;
    const __half* Blp = FULL ? Xlg + (size_t)b * xstride : nullptr;
    const size_t obase = (size_t)ksl * oslice;

    const int ar = tid >> 2, ak = (tid & 3) * 8;
    const int br = tid >> 4, bn = (tid & 15) * 8;
    const int quad = lane >> 3, r8 = lane & 7;
    const int qlow = (quad & 1) * 8, qhi = (quad >> 1) * 8;

    float c[2][4][4];
    #pragma unroll
    for (int i = 0; i < 2; i++)
        #pragma unroll
        for (int j = 0; j < 4; j++)
            #pragma unroll
            for (int e = 0; e < 4; e++) c[i][j][e] = 0.f;

    auto issue = [&](int s, int ch) {
        const int k0 = kg0 + ch * 32;
        const uint32_t st = sb + 2 * (s * STG);
        cpasync16(st + 2 * (OFF_AH + ar * A_ST + ak), Wb  + (size_t)(m0 + ar) * kfull + k0 + ak);
        cpasync16(st + 2 * (OFF_BH + br * B_ST + bn), Bhp + (size_t)(k0 + br) * npix + n0 + bn);
        if (FULL) {
            cpasync16(st + 2 * (OFF_AL + ar * A_ST + ak), Wlb + (size_t)(m0 + ar) * kfull + k0 + ak);
            cpasync16(st + 2 * (OFF_BL + br * B_ST + bn), Blp + (size_t)(k0 + br) * npix + n0 + bn);
        }
    };

    issue(0, 0); CP_COMMIT();
    issue(1, 1); CP_COMMIT();

    int s = 0, s2 = 2;    // current stage / issue stage (incremental mod 5)
    for (int ch = 0; ch < nch; ch++) {
        if (ch + 2 < nch) {
            issue(s2, ch + 2); CP_COMMIT();
            if (++s2 == NSTAGE) s2 = 0;
        }
        if (ch + 2 < nch)      cp_wait<2>();
        else if (ch + 1 < nch) cp_wait<1>();
        else                   cp_wait<0>();
        __syncthreads();      // single barrier per chunk

        const uint32_t sbase = sb + 2 * (s * STG);
        #pragma unroll
        for (int k16 = 0; k16 < 2; k16++) {
            uint32_t ah[2][4], al[2][4], bh[2][4], bl[2][4];
            #pragma unroll
            for (int mi = 0; mi < 2; mi++) {
                const uint32_t off = 2 * ((uint32_t)(wm * 32 + mi * 16 + r8 + qlow) * A_ST + k16 * 16 + qhi);
                ldsm4(ah[mi], sbase + 2 * OFF_AH + off);
                if (FULL) ldsm4(al[mi], sbase + 2 * OFF_AL + off);
            }
            #pragma unroll
            for (int ni = 0; ni < 2; ni++) {
                const uint32_t off = 2 * ((uint32_t)(k16 * 16 + r8 + qlow) * B_ST + wn * 32 + ni * 16 + qhi);
                ldsm4t(bh[ni], sbase + 2 * OFF_BH + off);
                if (FULL) ldsm4t(bl[ni], sbase + 2 * OFF_BL + off);
            }
            #pragma unroll
            for (int mi = 0; mi < 2; mi++)
                #pragma unroll
                for (int j = 0; j < 4; j++) {
                    const int ni = j >> 1, ss = (j & 1) * 2;
                    mma16816(c[mi][j], ah[mi], bh[ni][ss], bh[ni][ss + 1]);
                    if (FULL) {
                        mma16816(c[mi][j], ah[mi], bl[ni][ss], bl[ni][ss + 1]);
                        mma16816(c[mi][j], al[mi], bh[ni][ss], bh[ni][ss + 1]);
                    }
                }
        }
        if (++s == NSTAGE) s = 0;
    }

    #pragma unroll
    for (int mi = 0; mi < 2; mi++) {
        #pragma unroll
        for (int rr = 0; rr < 2; rr++) {
            const int m = m0 + wm * 32 + mi * 16 + (lane >> 2) + rr * 8;
            const float bi = bias ? __ldg(&bias[b * bstride + m]) : 0.f;
            const size_t rowoff = ((size_t)b * CCH + m) * npix + n0 + wn * 32 + (lane & 3) * 2;
            #pragma unroll
            for (int j = 0; j < 4; j++) {
                float2 v;
                v.x = c[mi][j][rr * 2 + 0] + bi;
                v.y = c[mi][j][rr * 2 + 1] + bi;
                if (RESID) {
                    float2 r = *(const float2*)&resid[rowoff + j * 8];
                    v.x += r.x; v.y += r.y;
                }
                if (HOUT) {
                    __half2 hv = __halves2half2(__float2half_rn(v.x), __float2half_rn(v.y));
                    *(__half2*)((__half*)out + obase + rowoff + j * 8) = hv;
                } else {
                    *(float2*)((float*)out + obase + rowoff + j * 8) = v;
                }
            }
        }
    }
}

// ---------------------------------------------------------------------------
__global__ void zero_s() { g_s[blockIdx.x * 512 + threadIdx.x] = 0.f; }

// prep_x: coalesced split fp32 -> fp16 hi/lo + row-sum atomic
__global__ void __launch_bounds__(256) prep_x(const float* __restrict__ src) {
    __shared__ float red[256];
    const size_t i = ((size_t)blockIdx.x * 256 + threadIdx.x) * 8;
    float4 v0 = *(const float4*)&src[i];
    float4 v1 = *(const float4*)&src[i + 4];
    const float v[8] = {v0.x, v0.y, v0.z, v0.w, v1.x, v1.y, v1.z, v1.w};
    __half h[8], l[8];
    float ps = 0.f;
    #pragma unroll
    for (int e = 0; e < 8; e++) {
        h[e] = __float2half_rn(v[e]);
        l[e] = __float2half_rn(v[e] - __half2float(h[e]));
        ps += v[e];
    }
    *(uint4*)&g_Xh[i] = *(const uint4*)h;
    *(uint4*)&g_Xl[i] = *(const uint4*)l;
    red[threadIdx.x] = ps; __syncthreads();
    for (int o = 128; o; o >>= 1) {
        if (threadIdx.x < o) red[threadIdx.x] += red[threadIdx.x + o];
        __syncthreads();
    }
    if (threadIdx.x == 0) atomicAdd(&g_s[blockIdx.x >> 1], red[0]);
}

// transpose + split, sourcing the (hi,lo) halves (32 MiB read instead of 64).
__global__ void __launch_bounds__(256) prep_xT() {
    __shared__ float s[32][33];
    const int n0 = blockIdx.x * 32, c0 = blockIdx.y * 32, b = blockIdx.z;
    const int tx = threadIdx.x, ty = threadIdx.y;
    #pragma unroll
    for (int i = 0; i < 4; i++) {
        const size_t idx = ((size_t)(b * CCH + c0 + ty + 8 * i)) * NPIX + n0 + tx;
        s[ty + 8 * i][tx] = __half2float(g_Xh[idx]) + __half2float(g_Xl[idx]);
    }
    __syncthreads();
    #pragma unroll
    for (int i = 0; i < 4; i++) {
        const float v = s[tx][ty + 8 * i];
        const __half hi = __float2half_rn(v);
        const size_t idx = ((size_t)b * NPIX + n0 + ty + 8 * i) * CCH + c0 + tx;
        g_XTh[idx] = hi;
        g_XTl[idx] = __float2half_rn(v - __half2float(hi));
    }
}

__global__ void __launch_bounds__(256) prep_w(
    const float* __restrict__ Wq, const float* __restrict__ Wk,
    const float* __restrict__ Wv, const float* __restrict__ Wo)
{
    const int m = blockIdx.y;
    const size_t t = (size_t)blockIdx.x * 256 + threadIdx.x;
    const float* W = (m == 0) ? Wq : (m == 1) ? Wk : (m == 2) ? Wv : Wo;
    const float v = W[t];
    const __half h = __float2half_rn(v);
    g_Wh[(size_t)m * CCH * CCH + t] = h;
    g_Wl[(size_t)m * CCH * CCH + t] = __float2half_rn(v - __half2float(h));
}

// sum SPLITK split-K partials, mirror lower triangle, split to fp16
__global__ void __launch_bounds__(256) splitG() {
    __shared__ float s[32][33];
    const int ti = blockIdx.x, tj = blockIdx.y, b = blockIdx.z;
    const int tx = threadIdx.x, ty = threadIdx.y;
    const size_t base = (size_t)b * CCH * CCH;
    const bool swap = (ti >> 2) > (tj >> 2);
    if (!swap) {
        #pragma unroll
        for (int k = 0; k < 4; k++) {
            const int r = ti * 32 + ty + 8 * k, cc = tj * 32 + tx;
            const size_t o = base + (size_t)r * CCH + cc;
            float v = 0.f;
            #pragma unroll
            for (int p = 0; p < SPLITK; p++) v += g_Gp[p][o];
            const __half hi = __float2half_rn(v);
            g_Gh[o] = hi; g_Gl[o] = __float2half_rn(v - __half2float(hi));
        }
    } else {
        #pragma unroll
        for (int k = 0; k < 4; k++) {
            const int r = tj * 32 + ty + 8 * k, cc = ti * 32 + tx;
            const size_t o = base + (size_t)r * CCH + cc;
            float v = 0.f;
            #pragma unroll
            for (int p = 0; p < SPLITK; p++) v += g_Gp[p][o];
            s[ty + 8 * k][tx] = v;
        }
        __syncthreads();
        #pragma unroll
        for (int k = 0; k < 4; k++) {
            const int r = ti * 32 + ty + 8 * k, cc = tj * 32 + tx;
            const float v = s[tx][ty + 8 * k];
            const __half hi = __float2half_rn(v);
            const size_t o = base + (size_t)r * CCH + cc;
            g_Gh[o] = hi; g_Gl[o] = __float2half_rn(v - __half2float(hi));
        }
    }
}

// qs = Wq s ; ks = Wk s  (grid.z selects matrix)
__global__ void __launch_bounds__(256) gemv_qk(
    const float* __restrict__ Wq, const float* __restrict__ Wk)
{
    const int b = blockIdx.y, m = blockIdx.x * 8 + (threadIdx.x >> 5), lane = threadIdx.x & 31;
    const float* W = blockIdx.z ? Wk : Wq;
    float* o = blockIdx.z ? g_ks : g_qs;
    const float* vb = g_s + b * 512;
    float acc = 0.f;
    for (int k = lane; k < 512; k += 32) acc += W[(size_t)m * 512 + k] * vb[k];
    #pragma unroll
    for (int off = 16; off; off >>= 1) acc += __shfl_down_sync(0xffffffffu, acc, off);
    if (lane == 0) o[b * 512 + m] = acc;
}

// bo2 = Wo by + bo
__global__ void __launch_bounds__(256) gemv_bo(
    const float* __restrict__ Wo, const float* __restrict__ bo)
{
    const int b = blockIdx.y, m = blockIdx.x * 8 + (threadIdx.x >> 5), lane = threadIdx.x & 31;
    const float* vb = g_by + b * 512;
    float acc = 0.f;
    for (int k = lane; k < 512; k += 32) acc += Wo[(size_t)m * 512 + k] * vb[k];
    #pragma unroll
    for (int off = 16; off; off >>= 1) acc += __shfl_down_sync(0xffffffffu, acc, off);
    if (lane == 0) g_bo2[b * 512 + m] = acc + bo[m];
}

// Fused: softmax(L(d)) (gamma-folded, kept in SMEM) then Wy rows + by.
__global__ void __launch_bounds__(256) lsoftmax_wy(
    const float* __restrict__ Wk, const float* __restrict__ bq,
    const float* __restrict__ bk, const float* __restrict__ gamma,
    const float* __restrict__ Wv, const float* __restrict__ bv)
{
    const int d = blockIdx.x, b = blockIdx.y;
    const int t = threadIdx.x, pair = t >> 2, h = pair >> 3, hp = pair & 7, cs = t & 3;

    const float* Ur = g_U + ((size_t)b * 512 + h * 64 + d) * 512;
    const float* Kr = Wk + (size_t)(hp * 64 + d) * 512;
    float acc = 0.f;
    for (int cc = cs; cc < 512; cc += 4) acc += Ur[cc] * Kr[cc];
    acc += __shfl_down_sync(0xffffffffu, acc, 2);
    acc += __shfl_down_sync(0xffffffffu, acc, 1);
    __shared__ float sL[64];
    __shared__ float a_s[64];
    if (cs == 0) {
        const int qi = h * 64 + d, ki = hp * 64 + d;
        const float Lv = acc + bq[qi] * g_ks[b * 512 + ki] + bk[ki] * g_qs[b * 512 + qi]
                       + 4096.f * bq[qi] * bk[ki];
        sL[pair] = Lv * 0.125f;
    }
    __syncthreads();
    if (t < 8) {
        float m = -INFINITY;
        #pragma unroll
        for (int j = 0; j < 8; j++) m = fmaxf(m, sL[t * 8 + j]);
        float e[8], ssum = 0.f;
        #pragma unroll
        for (int j = 0; j < 8; j++) { e[j] = expf(sL[t * 8 + j] - m); ssum += e[j]; }
        const float sc = gamma[0] / ssum;
        #pragma unroll
        for (int j = 0; j < 8; j++) a_s[t * 8 + j] = e[j] * sc;
    }
    __syncthreads();
    if (t < 8) {
        float s = 0.f;
        #pragma unroll
        for (int j = 0; j < 8; j++) s += a_s[t * 8 + j] * bv[j * 64 + d];
        g_by[b * 512 + t * 64 + d] = s;
    }
    for (int cc = t; cc < 512; cc += 256) {
        float v[8];
        #pragma unroll
        for (int j = 0; j < 8; j++) v[j] = Wv[(size_t)(j * 64 + d) * 512 + cc];
        #pragma unroll
        for (int hh = 0; hh < 8; hh++) {
            float y = 0.f;
            #pragma unroll
            for (int j = 0; j < 8; j++) y += a_s[hh * 8 + j] * v[j];
            g_Wyh[(size_t)b * CCH * CCH + (size_t)(hh * 64 + d) * 512 + cc] = __float2half_rn(y);
        }
    }
}

// ---------------------------------------------------------------------------
extern "C" void kernel_launch(void* const* d_in, const int* in_sizes, int n_in,
                              void* d_out, int out_size)
{
    const float* x  = (const float*)d_in[0];
    const float* Wq = (const float*)d_in[1];
    const float* bq = (const float*)d_in[2];
    const float* Wk = (const float*)d_in[3];
    const float* bk = (const float*)d_in[4];
    const float* Wv = (const float*)d_in[5];
    const float* bv = (const float*)d_in[6];
    const float* Wo = (const float*)d_in[7];
    const float* bo = (const float*)d_in[8];
    const float* gm = (const float*)d_in[9];
    float* out = (float*)d_out;

    __half *Xh, *Xl, *XTh, *XTl, *Wh, *Wl, *Gh, *Gl, *Wyh, *Mh;
    float *GpP, *UP, *bo2P;
    cudaGetSymbolAddress((void**)&Xh, g_Xh);   cudaGetSymbolAddress((void**)&Xl, g_Xl);
    cudaGetSymbolAddress((void**)&XTh, g_XTh); cudaGetSymbolAddress((void**)&XTl, g_XTl);
    cudaGetSymbolAddress((void**)&Wh, g_Wh);   cudaGetSymbolAddress((void**)&Wl, g_Wl);
    cudaGetSymbolAddress((void**)&Gh, g_Gh);   cudaGetSymbolAddress((void**)&Gl, g_Gl);
    cudaGetSymbolAddress((void**)&Wyh, g_Wyh); cudaGetSymbolAddress((void**)&Mh, g_Mh);
    cudaGetSymbolAddress((void**)&GpP, g_Gp);  cudaGetSymbolAddress((void**)&UP, g_U);
    cudaGetSymbolAddress((void**)&bo2P, g_bo2);

    static bool attr = false;
    if (!attr) {
        cudaFuncSetAttribute(hgemm<false, true,  true,  false>, cudaFuncAttributeMaxDynamicSharedMemorySize, SMEM_FULL);
        cudaFuncSetAttribute(hgemm<false, true,  false, false>, cudaFuncAttributeMaxDynamicSharedMemorySize, SMEM_FULL);
        cudaFuncSetAttribute(hgemm<false, false, false, true >, cudaFuncAttributeMaxDynamicSharedMemorySize, SMEM_LITE);
        cudaFuncSetAttribute(hgemm<true,  false, false, false>, cudaFuncAttributeMaxDynamicSharedMemorySize, SMEM_LITE);
        attr = true;
    }

    const size_t WS = (size_t)CCH * CCH;
    const size_t XS = (size_t)CCH * NPIX;

    zero_s<<<8, 512>>>();
    prep_x<<<(unsigned)((size_t)BATCH * XS / 2048), 256>>>(x);
    prep_xT<<<dim3(NPIX / 32, CCH / 32, BATCH), dim3(32, 8)>>>();
    prep_w<<<dim3(CCH * CCH / 256, 4), 256>>>(Wq, Wk, Wv, Wo);
    gemv_qk<<<dim3(64, BATCH, 2), 256>>>(Wq, Wk);

    // Gram: G_b = x x^T, upper-triangle tiles, split-K8 (3-pass)
    hgemm<false, true, true, false><<<dim3(10, 1, 8 * SPLITK), 512, SMEM_FULL>>>(
        Xh, Xl, XTh, XTl, nullptr, nullptr, GpP,
        512, NPIX, 128 / SPLITK, XS, XS, 0, (size_t)BATCH * WS);
    splitG<<<dim3(16, 16, BATCH), dim3(32, 8)>>>();

    // U_b = Wq G_b (3-pass)
    hgemm<false, true, false, false><<<dim3(4, 4, BATCH), 512, SMEM_FULL>>>(
        Wh + 0 * WS, Wl + 0 * WS, Gh, Gl, nullptr, nullptr, UP,
        512, 512, 16, 0, WS, 0, 0);

    lsoftmax_wy<<<dim3(64, BATCH), 256>>>(Wk, bq, bk, gm, Wv, bv);
    gemv_bo<<<dim3(64, BATCH), 256>>>(Wo, bo);

    // M_b = Wo * Wy_b (1-pass), fp16 output directly
    hgemm<false, false, false, true><<<dim3(4, 4, BATCH), 512, SMEM_LITE>>>(
        Wh + 3 * WS, nullptr, Wyh, nullptr, nullptr, nullptr, Mh,
        512, 512, 16, 0, WS, 0, 0);

    // out = M_b x + bo2_b + x (1-pass)
    hgemm<true, false, false, false><<<dim3(NPIX / 128, 4, BATCH), 512, SMEM_LITE>>>(
        Mh, nullptr, Xh, nullptr, bo2P, x, out,
        NPIX, 512, 16, WS, XS, 512, 0);
}

// round 15
// speedup vs baseline: 1.1712x; 1.0269x over previous
#include <cuda_runtime.h>
#include <cuda_fp16.h>
#include <math.h>
#include <stdint.h>

#define CCH   512
#define NPIX  4096
#define BATCH 8
#define SPLITK 8

// ---------------- scratch ----------------
__device__ __half g_Xh[(size_t)BATCH * CCH * NPIX];
__device__ __half g_Xl[(size_t)BATCH * CCH * NPIX];
__device__ __half g_Wh[4 * CCH * CCH];
__device__ __half g_Wl[4 * CCH * CCH];
__device__ float  g_s [BATCH * CCH];
__device__ float  g_qs[BATCH * CCH];
__device__ float  g_ks[BATCH * CCH];
__device__ float  g_by[BATCH * CCH];
__device__ float  g_bo2[BATCH * CCH];
__device__ float  g_Gp[SPLITK][(size_t)BATCH * CCH * CCH];  // split-K partials
__device__ __half g_Gh[(size_t)BATCH * CCH * CCH];
__device__ __half g_Gl[(size_t)BATCH * CCH * CCH];
__device__ float  g_U [(size_t)BATCH * CCH * CCH];
__device__ __half g_Wyh[(size_t)BATCH * CCH * CCH];
__device__ __half g_Mh[(size_t)BATCH * CCH * CCH];

__constant__ int c_pm[10] = {0,0,0,0,1,1,1,2,2,3};
__constant__ int c_pn[10] = {0,1,2,3,1,2,3,2,3,3};

// ---------------- helpers ----------------
__device__ __forceinline__ uint32_t smem_u32(const void* p) {
    uint32_t a;
    asm("{ .reg .u64 t; cvta.to.shared.u64 t, %1; cvt.u32.u64 %0, t; }" : "=r"(a) : "l"(p));
    return a;
}
__device__ __forceinline__ void cpasync16(uint32_t dst, const void* src) {
    asm volatile("cp.async.cg.shared.global [%0], [%1], 16;" :: "r"(dst), "l"(src));
}
#define CP_COMMIT() asm volatile("cp.async.commit_group;" ::: "memory")
template<int N> __device__ __forceinline__ void cp_wait() {
    asm volatile("cp.async.wait_group %0;" :: "n"(N) : "memory");
}
__device__ __forceinline__ void ldsm4(uint32_t* r, uint32_t addr) {
    asm volatile("ldmatrix.sync.aligned.m8n8.x4.shared.b16 {%0,%1,%2,%3}, [%4];"
                 : "=r"(r[0]), "=r"(r[1]), "=r"(r[2]), "=r"(r[3]) : "r"(addr));
}
__device__ __forceinline__ void ldsm4t(uint32_t* r, uint32_t addr) {
    asm volatile("ldmatrix.sync.aligned.m8n8.x4.trans.shared.b16 {%0,%1,%2,%3}, [%4];"
                 : "=r"(r[0]), "=r"(r[1]), "=r"(r[2]), "=r"(r[3]) : "r"(addr));
}
__device__ __forceinline__ void mma16816(float* c, const uint32_t* a, uint32_t b0, uint32_t b1) {
    asm volatile("mma.sync.aligned.m16n8k16.row.col.f32.f16.f16.f32 "
                 "{%0,%1,%2,%3}, {%4,%5,%6,%7}, {%8,%9}, {%0,%1,%2,%3};"
                 : "+f"(c[0]), "+f"(c[1]), "+f"(c[2]), "+f"(c[3])
                 : "r"(a[0]), "r"(a[1]), "r"(a[2]), "r"(a[3]), "r"(b0), "r"(b1));
}

#define A_ST 40
#define B_ST 136
#define A_MAT (128 * A_ST)              // 5120 halfs
#define B_MAT (32 * B_ST)               // 4352 halfs
#define STG_FULL (2 * A_MAT + 2 * B_MAT)   // 18944 halfs
#define STG_LITE (A_MAT + B_MAT)           //  9472 halfs
#define STG_BROW (4 * A_MAT)               // 20480 halfs (B tiles are A-shaped)
#define NSTAGE 5
#define SMEM_FULL (NSTAGE * STG_FULL * 2)  // 189440 B
#define SMEM_LITE (NSTAGE * STG_LITE * 2)  //  94720 B
#define SMEM_BROW (NSTAGE * STG_BROW * 2)  // 204800 B

// ---------------------------------------------------------------------------
// hgemm: out[b][m][n] = sum_k W[m,k] * X[b][k][n] (+bias[b][m]) (+resid)
// FULL: 3-pass double-fp16. TRI: upper-triangle tile remap. HOUT: fp16 out.
// BROW: B operand sourced from [n][k] ROW-major global (X rows), staged with
//       the A-style map (A_ST stride, A_MAT-sized tiles) and loaded with plain
//       ldmatrix; fragment pairing becomes (r0,r2)/(r1,r3). Stage layout is
//       resized accordingly (this was the R14 OOB bug).
// 5-stage cp.async pipeline, issue-ahead-2, ONE barrier per K-chunk.
// ---------------------------------------------------------------------------
template<bool RESID, bool FULL, bool TRI, bool HOUT, bool BROW>
__global__ void __launch_bounds__(512, 1) hgemm(
    const __half* __restrict__ Whg, const __half* __restrict__ Wlg,
    const __half* __restrict__ Xhg, const __half* __restrict__ Xlg,
    const float* __restrict__ bias, const float* __restrict__ resid,
    void* __restrict__ out,
    int npix, int kfull, int nch,
    size_t wstride, size_t xstride, int bstride, size_t oslice)
{
    extern __shared__ __half sm[];
    const uint32_t sb = smem_u32(sm);
    constexpr int STG    = BROW ? STG_BROW : (FULL ? STG_FULL : STG_LITE);
    constexpr int OFF_AH = 0, OFF_AL = A_MAT;
    constexpr int OFF_BH = BROW ? 2 * A_MAT : (FULL ? 2 * A_MAT : A_MAT);
    constexpr int OFF_BL = BROW ? 3 * A_MAT : 2 * A_MAT + B_MAT;

    const int tid = threadIdx.x, lane = tid & 31, wid = tid >> 5;
    const int wm = wid >> 2, wn = wid & 3;
    const int b = blockIdx.z & 7, ksl = blockIdx.z >> 3;
    const int m0 = (TRI ? c_pm[blockIdx.x] : (int)blockIdx.y) * 128;
    const int n0 = (TRI ? c_pn[blockIdx.x] : (int)blockIdx.x) * 128;
    const int kg0 = ksl * nch * 32;
    const __half* Wb  = Whg + (size_t)b * wstride;
    const __half* Wlb = FULL ? Wlg + (size_t)b * wstride : nullptr;
    const __half* Bhp = Xhg + (size_t)b * xstride;
    const __half* Blp = FULL ? Xlg + (size_t)b * xstride : nullptr;
    const size_t obase = (size_t)ksl * oslice;

    const int ar = tid >> 2, ak = (tid & 3) * 8;
    const int br = tid >> 4, bn = (tid & 15) * 8;
    const int quad = lane >> 3, r8 = lane & 7;
    const int qlow = (quad & 1) * 8, qhi = (quad >> 1) * 8;

    float c[2][4][4];
    #pragma unroll
    for (int i = 0; i < 2; i++)
        #pragma unroll
        for (int j = 0; j < 4; j++)
            #pragma unroll
            for (int e = 0; e < 4; e++) c[i][j][e] = 0.f;

    auto issue = [&](int s, int ch) {
        const int k0 = kg0 + ch * 32;
        const uint32_t st = sb + 2 * (s * STG);
        cpasync16(st + 2 * (OFF_AH + ar * A_ST + ak), Wb + (size_t)(m0 + ar) * kfull + k0 + ak);
        if (BROW) {
            // B tile: 128 rows (n) x 32 halfs (k), A-style staging
            cpasync16(st + 2 * (OFF_BH + ar * A_ST + ak), Bhp + (size_t)(n0 + ar) * kfull + k0 + ak);
        } else {
            cpasync16(st + 2 * (OFF_BH + br * B_ST + bn), Bhp + (size_t)(k0 + br) * npix + n0 + bn);
        }
        if (FULL) {
            cpasync16(st + 2 * (OFF_AL + ar * A_ST + ak), Wlb + (size_t)(m0 + ar) * kfull + k0 + ak);
            if (BROW) {
                cpasync16(st + 2 * (OFF_BL + ar * A_ST + ak), Blp + (size_t)(n0 + ar) * kfull + k0 + ak);
            } else {
                cpasync16(st + 2 * (OFF_BL + br * B_ST + bn), Blp + (size_t)(k0 + br) * npix + n0 + bn);
            }
        }
    };

    issue(0, 0); CP_COMMIT();
    issue(1, 1); CP_COMMIT();

    int s = 0, s2 = 2;
    for (int ch = 0; ch < nch; ch++) {
        if (ch + 2 < nch) {
            issue(s2, ch + 2); CP_COMMIT();
            if (++s2 == NSTAGE) s2 = 0;
        }
        if (ch + 2 < nch)      cp_wait<2>();
        else if (ch + 1 < nch) cp_wait<1>();
        else                   cp_wait<0>();
        __syncthreads();      // single barrier per chunk

        const uint32_t sbase = sb + 2 * (s * STG);
        #pragma unroll
        for (int k16 = 0; k16 < 2; k16++) {
            uint32_t ah[2][4], al[2][4], bh[2][4], bl[2][4];
            #pragma unroll
            for (int mi = 0; mi < 2; mi++) {
                const uint32_t off = 2 * ((uint32_t)(wm * 32 + mi * 16 + r8 + qlow) * A_ST + k16 * 16 + qhi);
                ldsm4(ah[mi], sbase + 2 * OFF_AH + off);
                if (FULL) ldsm4(al[mi], sbase + 2 * OFF_AL + off);
            }
            #pragma unroll
            for (int ni = 0; ni < 2; ni++) {
                if (BROW) {
                    const uint32_t off = 2 * ((uint32_t)(wn * 32 + ni * 16 + r8 + qlow) * A_ST + k16 * 16 + qhi);
                    ldsm4(bh[ni], sbase + 2 * OFF_BH + off);
                    if (FULL) ldsm4(bl[ni], sbase + 2 * OFF_BL + off);
                } else {
                    const uint32_t off = 2 * ((uint32_t)(k16 * 16 + r8 + qlow) * B_ST + wn * 32 + ni * 16 + qhi);
                    ldsm4t(bh[ni], sbase + 2 * OFF_BH + off);
                    if (FULL) ldsm4t(bl[ni], sbase + 2 * OFF_BL + off);
                }
            }
            #pragma unroll
            for (int mi = 0; mi < 2; mi++)
                #pragma unroll
                for (int j = 0; j < 4; j++) {
                    const int ni = j >> 1;
                    // trans path: pairs (0,1)/(2,3); BROW path: (0,2)/(1,3)
                    const int p0 = BROW ? (j & 1)       : (j & 1) * 2;
                    const int p1 = BROW ? (j & 1) + 2   : (j & 1) * 2 + 1;
                    mma16816(c[mi][j], ah[mi], bh[ni][p0], bh[ni][p1]);
                    if (FULL) {
                        mma16816(c[mi][j], ah[mi], bl[ni][p0], bl[ni][p1]);
                        mma16816(c[mi][j], al[mi], bh[ni][p0], bh[ni][p1]);
                    }
                }
        }
        if (++s == NSTAGE) s = 0;
    }

    #pragma unroll
    for (int mi = 0; mi < 2; mi++) {
        #pragma unroll
        for (int rr = 0; rr < 2; rr++) {
            const int m = m0 + wm * 32 + mi * 16 + (lane >> 2) + rr * 8;
            const float bi = bias ? __ldg(&bias[b * bstride + m]) : 0.f;
            const size_t rowoff = ((size_t)b * CCH + m) * npix + n0 + wn * 32 + (lane & 3) * 2;
            #pragma unroll
            for (int j = 0; j < 4; j++) {
                float2 v;
                v.x = c[mi][j][rr * 2 + 0] + bi;
                v.y = c[mi][j][rr * 2 + 1] + bi;
                if (RESID) {
                    float2 r = *(const float2*)&resid[rowoff + j * 8];
                    v.x += r.x; v.y += r.y;
                }
                if (HOUT) {
                    __half2 hv = __halves2half2(__float2half_rn(v.x), __float2half_rn(v.y));
                    *(__half2*)((__half*)out + obase + rowoff + j * 8) = hv;
                } else {
                    *(float2*)((float*)out + obase + rowoff + j * 8) = v;
                }
            }
        }
    }
}

// ---------------------------------------------------------------------------
__global__ void zero_s() { g_s[blockIdx.x * 512 + threadIdx.x] = 0.f; }

// prep_x: coalesced split fp32 -> fp16 hi/lo + row-sum atomic
__global__ void __launch_bounds__(256) prep_x(const float* __restrict__ src) {
    __shared__ float red[256];
    const size_t i = ((size_t)blockIdx.x * 256 + threadIdx.x) * 8;
    float4 v0 = *(const float4*)&src[i];
    float4 v1 = *(const float4*)&src[i + 4];
    const float v[8] = {v0.x, v0.y, v0.z, v0.w, v1.x, v1.y, v1.z, v1.w};
    __half h[8], l[8];
    float ps = 0.f;
    #pragma unroll
    for (int e = 0; e < 8; e++) {
        h[e] = __float2half_rn(v[e]);
        l[e] = __float2half_rn(v[e] - __half2float(h[e]));
        ps += v[e];
    }
    *(uint4*)&g_Xh[i] = *(const uint4*)h;
    *(uint4*)&g_Xl[i] = *(const uint4*)l;
    red[threadIdx.x] = ps; __syncthreads();
    for (int o = 128; o; o >>= 1) {
        if (threadIdx.x < o) red[threadIdx.x] += red[threadIdx.x + o];
        __syncthreads();
    }
    if (threadIdx.x == 0) atomicAdd(&g_s[blockIdx.x >> 1], red[0]);
}

__global__ void __launch_bounds__(256) prep_w(
    const float* __restrict__ Wq, const float* __restrict__ Wk,
    const float* __restrict__ Wv, const float* __restrict__ Wo)
{
    const int m = blockIdx.y;
    const size_t t = (size_t)blockIdx.x * 256 + threadIdx.x;
    const float* W = (m == 0) ? Wq : (m == 1) ? Wk : (m == 2) ? Wv : Wo;
    const float v = W[t];
    const __half h = __float2half_rn(v);
    g_Wh[(size_t)m * CCH * CCH + t] = h;
    g_Wl[(size_t)m * CCH * CCH + t] = __float2half_rn(v - __half2float(h));
}

// sum SPLITK split-K partials, mirror lower triangle, split to fp16
__global__ void __launch_bounds__(256) splitG() {
    __shared__ float s[32][33];
    const int ti = blockIdx.x, tj = blockIdx.y, b = blockIdx.z;
    const int tx = threadIdx.x, ty = threadIdx.y;
    const size_t base = (size_t)b * CCH * CCH;
    const bool swap = (ti >> 2) > (tj >> 2);
    if (!swap) {
        #pragma unroll
        for (int k = 0; k < 4; k++) {
            const int r = ti * 32 + ty + 8 * k, cc = tj * 32 + tx;
            const size_t o = base + (size_t)r * CCH + cc;
            float v = 0.f;
            #pragma unroll
            for (int p = 0; p < SPLITK; p++) v += g_Gp[p][o];
            const __half hi = __float2half_rn(v);
            g_Gh[o] = hi; g_Gl[o] = __float2half_rn(v - __half2float(hi));
        }
    } else {
        #pragma unroll
        for (int k = 0; k < 4; k++) {
            const int r = tj * 32 + ty + 8 * k, cc = ti * 32 + tx;
            const size_t o = base + (size_t)r * CCH + cc;
            float v = 0.f;
            #pragma unroll
            for (int p = 0; p < SPLITK; p++) v += g_Gp[p][o];
            s[ty + 8 * k][tx] = v;
        }
        __syncthreads();
        #pragma unroll
        for (int k = 0; k < 4; k++) {
            const int r = ti * 32 + ty + 8 * k, cc = tj * 32 + tx;
            const float v = s[tx][ty + 8 * k];
            const __half hi = __float2half_rn(v);
            const size_t o = base + (size_t)r * CCH + cc;
            g_Gh[o] = hi; g_Gl[o] = __float2half_rn(v - __half2float(hi));
        }
    }
}

// qs = Wq s ; ks = Wk s  (grid.z selects matrix)
__global__ void __launch_bounds__(256) gemv_qk(
    const float* __restrict__ Wq, const float* __restrict__ Wk)
{
    const int b = blockIdx.y, m = blockIdx.x * 8 + (threadIdx.x >> 5), lane = threadIdx.x & 31;
    const float* W = blockIdx.z ? Wk : Wq;
    float* o = blockIdx.z ? g_ks : g_qs;
    const float* vb = g_s + b * 512;
    float acc = 0.f;
    for (int k = lane; k < 512; k += 32) acc += W[(size_t)m * 512 + k] * vb[k];
    #pragma unroll
    for (int off = 16; off; off >>= 1) acc += __shfl_down_sync(0xffffffffu, acc, off);
    if (lane == 0) o[b * 512 + m] = acc;
}

// bo2 = Wo by + bo
__global__ void __launch_bounds__(256) gemv_bo(
    const float* __restrict__ Wo, const float* __restrict__ bo)
{
    const int b = blockIdx.y, m = blockIdx.x * 8 + (threadIdx.x >> 5), lane = threadIdx.x & 31;
    const float* vb = g_by + b * 512;
    float acc = 0.f;
    for (int k = lane; k < 512; k += 32) acc += Wo[(size_t)m * 512 + k] * vb[k];
    #pragma unroll
    for (int off = 16; off; off >>= 1) acc += __shfl_down_sync(0xffffffffu, acc, off);
    if (lane == 0) g_bo2[b * 512 + m] = acc + bo[m];
}

// Fused: softmax(L(d)) (gamma-folded, kept in SMEM) then Wy rows + by.
__global__ void __launch_bounds__(256) lsoftmax_wy(
    const float* __restrict__ Wk, const float* __restrict__ bq,
    const float* __restrict__ bk, const float* __restrict__ gamma,
    const float* __restrict__ Wv, const float* __restrict__ bv)
{
    const int d = blockIdx.x, b = blockIdx.y;
    const int t = threadIdx.x, pair = t >> 2, h = pair >> 3, hp = pair & 7, cs = t & 3;

    const float* Ur = g_U + ((size_t)b * 512 + h * 64 + d) * 512;
    const float* Kr = Wk + (size_t)(hp * 64 + d) * 512;
    float acc = 0.f;
    for (int cc = cs; cc < 512; cc += 4) acc += Ur[cc] * Kr[cc];
    acc += __shfl_down_sync(0xffffffffu, acc, 2);
    acc += __shfl_down_sync(0xffffffffu, acc, 1);
    __shared__ float sL[64];
    __shared__ float a_s[64];
    if (cs == 0) {
        const int qi = h * 64 + d, ki = hp * 64 + d;
        const float Lv = acc + bq[qi] * g_ks[b * 512 + ki] + bk[ki] * g_qs[b * 512 + qi]
                       + 4096.f * bq[qi] * bk[ki];
        sL[pair] = Lv * 0.125f;
    }
    __syncthreads();
    if (t < 8) {
        float m = -INFINITY;
        #pragma unroll
        for (int j = 0; j < 8; j++) m = fmaxf(m, sL[t * 8 + j]);
        float e[8], ssum = 0.f;
        #pragma unroll
        for (int j = 0; j < 8; j++) { e[j] = expf(sL[t * 8 + j] - m); ssum += e[j]; }
        const float sc = gamma[0] / ssum;
        #pragma unroll
        for (int j = 0; j < 8; j++) a_s[t * 8 + j] = e[j] * sc;
    }
    __syncthreads();
    if (t < 8) {
        float s = 0.f;
        #pragma unroll
        for (int j = 0; j < 8; j++) s += a_s[t * 8 + j] * bv[j * 64 + d];
        g_by[b * 512 + t * 64 + d] = s;
    }
    for (int cc = t; cc < 512; cc += 256) {
        float v[8];
        #pragma unroll
        for (int j = 0; j < 8; j++) v[j] = Wv[(size_t)(j * 64 + d) * 512 + cc];
        #pragma unroll
        for (int hh = 0; hh < 8; hh++) {
            float y = 0.f;
            #pragma unroll
            for (int j = 0; j < 8; j++) y += a_s[hh * 8 + j] * v[j];
            g_Wyh[(size_t)b * CCH * CCH + (size_t)(hh * 64 + d) * 512 + cc] = __float2half_rn(y);
        }
    }
}

// ---------------------------------------------------------------------------
extern "C" void kernel_launch(void* const* d_in, const int* in_sizes, int n_in,
                              void* d_out, int out_size)
{
    const float* x  = (const float*)d_in[0];
    const float* Wq = (const float*)d_in[1];
    const float* bq = (const float*)d_in[2];
    const float* Wk = (const float*)d_in[3];
    const float* bk = (const float*)d_in[4];
    const float* Wv = (const float*)d_in[5];
    const float* bv = (const float*)d_in[6];
    const float* Wo = (const float*)d_in[7];
    const float* bo = (const float*)d_in[8];
    const float* gm = (const float*)d_in[9];
    float* out = (float*)d_out;

    __half *Xh, *Xl, *Wh, *Wl, *Gh, *Gl, *Wyh, *Mh;
    float *GpP, *UP, *bo2P;
    cudaGetSymbolAddress((void**)&Xh, g_Xh);   cudaGetSymbolAddress((void**)&Xl, g_Xl);
    cudaGetSymbolAddress((void**)&Wh, g_Wh);   cudaGetSymbolAddress((void**)&Wl, g_Wl);
    cudaGetSymbolAddress((void**)&Gh, g_Gh);   cudaGetSymbolAddress((void**)&Gl, g_Gl);
    cudaGetSymbolAddress((void**)&Wyh, g_Wyh); cudaGetSymbolAddress((void**)&Mh, g_Mh);
    cudaGetSymbolAddress((void**)&GpP, g_Gp);  cudaGetSymbolAddress((void**)&UP, g_U);
    cudaGetSymbolAddress((void**)&bo2P, g_bo2);

    static bool attr = false;
    if (!attr) {
        cudaFuncSetAttribute(hgemm<false, true,  true,  false, true >, cudaFuncAttributeMaxDynamicSharedMemorySize, SMEM_BROW);
        cudaFuncSetAttribute(hgemm<false, true,  false, false, false>, cudaFuncAttributeMaxDynamicSharedMemorySize, SMEM_FULL);
        cudaFuncSetAttribute(hgemm<false, false, false, true,  false>, cudaFuncAttributeMaxDynamicSharedMemorySize, SMEM_LITE);
        cudaFuncSetAttribute(hgemm<true,  false, false, false, false>, cudaFuncAttributeMaxDynamicSharedMemorySize, SMEM_LITE);
        attr = true;
    }

    const size_t WS = (size_t)CCH * CCH;
    const size_t XS = (size_t)CCH * NPIX;

    zero_s<<<8, 512>>>();
    prep_x<<<(unsigned)((size_t)BATCH * XS / 2048), 256>>>(x);
    prep_w<<<dim3(CCH * CCH / 256, 4), 256>>>(Wq, Wk, Wv, Wo);
    gemv_qk<<<dim3(64, BATCH, 2), 256>>>(Wq, Wk);

    // Gram: G_b = x x^T, upper-triangle tiles, split-K8 (3-pass), BROW B path
    // (both operands read straight from Xh/Xl — no transposed copy needed)
    hgemm<false, true, true, false, true><<<dim3(10, 1, 8 * SPLITK), 512, SMEM_BROW>>>(
        Xh, Xl, Xh, Xl, nullptr, nullptr, GpP,
        512, NPIX, 128 / SPLITK, XS, XS, 0, (size_t)BATCH * WS);
    splitG<<<dim3(16, 16, BATCH), dim3(32, 8)>>>();

    // U_b = Wq G_b (3-pass)
    hgemm<false, true, false, false, false><<<dim3(4, 4, BATCH), 512, SMEM_FULL>>>(
        Wh + 0 * WS, Wl + 0 * WS, Gh, Gl, nullptr, nullptr, UP,
        512, 512, 16, 0, WS, 0, 0);

    lsoftmax_wy<<<dim3(64, BATCH), 256>>>(Wk, bq, bk, gm, Wv, bv);
    gemv_bo<<<dim3(64, BATCH), 256>>>(Wo, bo);

    // M_b = Wo * Wy_b (1-pass), fp16 output directly
    hgemm<false, false, false, true, false><<<dim3(4, 4, BATCH), 512, SMEM_LITE>>>(
        Wh + 3 * WS, nullptr, Wyh, nullptr, nullptr, nullptr, Mh,
        512, 512, 16, 0, WS, 0, 0);

    // out = M_b x + bo2_b + x (1-pass)
    hgemm<true, false, false, false, false><<<dim3(NPIX / 128, 4, BATCH), 512, SMEM_LITE>>>(
        Mh, nullptr, Xh, nullptr, bo2P, x, out,
        NPIX, 512, 16, WS, XS, 512, 0);
}